// round 14
// baseline (speedup 1.0000x reference)
#include <cuda_runtime.h>
#include <cuda_fp16.h>
#include <cuda_bf16.h>
#include <cstdint>

// Problem constants
#define NN   8192
#define FIN  512
#define FOUT 64
#define NF   8                // 64 N cols / 8 per mma
#define SPLITS 4
#define JPER  (NN / SPLITS)   // 2048 j per split
#define BK    128             // j per iteration (two 64-j halves)
#define CHUNKS (JPER / BK)    // 16 iterations
#define BM   128              // rows per k3 block
#define PAD  136              // k3 smem row stride in halves (272B, ldmatrix conflict-free)
#define PADH 72               // k2 transpose tile stride
#define KQ   4                // k1 K-split factor

// -------- scratch (static device globals; no allocations allowed) --------
__device__ float  g_hp[KQ * NN * FOUT];          // 8.4 MB per-K-quarter h partials
__device__ float2 g_row[NN];                     // (exp(f1), exp(0.2 f1))
__device__ float2 g_col[NN];                     // (exp(f2), exp(0.2 f2))
__device__ __half g_hextT[FOUT * NN];            // 1 MB  transposed h fp16
__device__ float  g_partial[SPLITS * NN * FOUT]; // 8.4 MB per-split numerators
__device__ float  g_den[SPLITS * NN];            // per-split denominators
__device__ int    g_dummy_sink;

// -------- packed f32x2 FMA (Blackwell) --------
#define FMA_F32X2(d, a, b, c) \
    asm("fma.rn.f32x2 %0, %1, %2, %3;" : "=l"(d) : "l"(a), "l"(b), "l"(c))

// fp16-accumulator mma
__device__ __forceinline__ void mma16816h(uint32_t* c, const uint32_t* a,
                                          const uint32_t* b) {
    asm volatile(
        "mma.sync.aligned.m16n8k16.row.col.f16.f16.f16.f16 "
        "{%0,%1}, {%2,%3,%4,%5}, {%6,%7}, {%0,%1};"
        : "+r"(c[0]), "+r"(c[1])
        : "r"(a[0]), "r"(a[1]), "r"(a[2]), "r"(a[3]), "r"(b[0]), "r"(b[1]));
}

__device__ __forceinline__ void ldsm_x4(uint32_t& r0, uint32_t& r1, uint32_t& r2,
                                        uint32_t& r3, uint32_t addr) {
    asm volatile("ldmatrix.sync.aligned.m8n8.x4.shared.b16 {%0,%1,%2,%3}, [%4];"
                 : "=r"(r0), "=r"(r1), "=r"(r2), "=r"(r3) : "r"(addr));
}

__device__ __forceinline__ uint32_t smem_u32(const void* p) {
    uint32_t a;
    asm("{ .reg .u64 t; cvta.to.shared.u64 t, %1; cvt.u32.u64 %0, t; }"
        : "=r"(a) : "l"(p));
    return a;
}

// exp(lrelu(f1+f2)) = max(EA*EC, EB*ED)  (exp is monotone) ; mask via fp mul
__device__ __forceinline__ float wgen(float2 rv, float2 c, int m) {
    float w = fmaxf(rv.x * c.x, rv.y * c.y);
    return w * __int_as_float(m * 0x3F800000);
}

__device__ __forceinline__ uint32_t packh2(float lo, float hi) {
    __half2 h = __floats2half2_rn(lo, hi);
    return *(uint32_t*)&h;
}

// ==================== K0: dummy (keeps profiler aligned on k3) ===================
__global__ void k0_dummy() {
    if (threadIdx.x == 1024) g_dummy_sink = 1;
}

// ==================== K1: h = inp @ W  (fp32, f32x2, K split 4-ways) ============
__global__ __launch_bounds__(256) void k1_gemm(const float* __restrict__ inp,
                                               const float* __restrict__ W) {
    __shared__ float inp_s[64][68];
    __shared__ float w_sT[64][66];    // stride 66: conflict-free b-operand LDS.64
    const int t  = threadIdx.x;
    const int i0 = blockIdx.x * 64;
    const int k0 = blockIdx.y * (FIN / KQ);
    const int tx = t & 15;
    const int ty = t >> 4;

    unsigned long long acc2[4][4];
#pragma unroll
    for (int q = 0; q < 4; q++)
#pragma unroll
        for (int c = 0; c < 4; c++) acc2[q][c] = 0ULL;

    for (int kc = k0; kc < k0 + FIN / KQ; kc += 64) {
#pragma unroll
        for (int m = 0; m < 4; m++) {
            int lin = t + 256 * m;
            int row = lin >> 4, seg = lin & 15;
            float4 v  = *(const float4*)&inp[(i0 + row) * FIN + kc + seg * 4];
            *(float4*)&inp_s[row][seg * 4] = v;
            float4 wv = *(const float4*)&W[(kc + row) * FOUT + seg * 4];
            w_sT[seg * 4 + 0][row] = wv.x;
            w_sT[seg * 4 + 1][row] = wv.y;
            w_sT[seg * 4 + 2][row] = wv.z;
            w_sT[seg * 4 + 3][row] = wv.w;
        }
        __syncthreads();
#pragma unroll 4
        for (int kk = 0; kk < 64; kk += 2) {
            unsigned long long a2[4], b2[4];
#pragma unroll
            for (int q = 0; q < 4; q++)
                a2[q] = *(const unsigned long long*)&inp_s[ty * 4 + q][kk];
#pragma unroll
            for (int c = 0; c < 4; c++)
                b2[c] = *(const unsigned long long*)&w_sT[tx * 4 + c][kk];
#pragma unroll
            for (int q = 0; q < 4; q++)
#pragma unroll
                for (int c = 0; c < 4; c++)
                    FMA_F32X2(acc2[q][c], a2[q], b2[c], acc2[q][c]);
        }
        __syncthreads();
    }
    float* HP = &g_hp[(size_t)blockIdx.y * NN * FOUT];
#pragma unroll
    for (int q = 0; q < 4; q++)
#pragma unroll
        for (int c = 0; c < 4; c++) {
            float lo, hi;
            asm("mov.b64 {%0,%1}, %2;" : "=f"(lo), "=f"(hi) : "l"(acc2[q][c]));
            HP[(size_t)(i0 + ty * 4 + q) * FOUT + tx * 4 + c] = lo + hi;
        }
}

// ==================== K2: sum quarters, exp factors, COALESCED hT transpose =====
__global__ __launch_bounds__(256) void k2_prep(const float* __restrict__ a_vec) {
    __shared__ __half hh[64][PADH];
    __shared__ float as1[64], as2[64];

    const int t  = threadIdx.x;
    const int ib = blockIdx.x * 64;
    const int rl = t >> 2;          // local row 0..63
    const int cs = (t & 3) * 16;    // col segment

    if (t < 64)  as1[t] = a_vec[t];
    else if (t < 128) as2[t - 64] = a_vec[t];
    __syncthreads();

    float h[16];
#pragma unroll
    for (int p = 0; p < 4; p++) {
        float4 v = *(const float4*)&g_hp[(size_t)(ib + rl) * FOUT + cs + p * 4];
#pragma unroll
        for (int q = 1; q < KQ; q++) {
            float4 u = *(const float4*)&g_hp[(size_t)q * NN * FOUT +
                                             (size_t)(ib + rl) * FOUT + cs + p * 4];
            v.x += u.x; v.y += u.y; v.z += u.z; v.w += u.w;
        }
        h[p * 4 + 0] = v.x; h[p * 4 + 1] = v.y; h[p * 4 + 2] = v.z; h[p * 4 + 3] = v.w;
    }

    float s1 = 0.f, s2 = 0.f;
#pragma unroll
    for (int c = 0; c < 16; c++) {
        s1 += h[c] * as1[cs + c];
        s2 += h[c] * as2[cs + c];
    }
    s1 += __shfl_xor_sync(0xffffffffu, s1, 1);
    s1 += __shfl_xor_sync(0xffffffffu, s1, 2);
    s2 += __shfl_xor_sync(0xffffffffu, s2, 1);
    s2 += __shfl_xor_sync(0xffffffffu, s2, 2);
    if ((t & 3) == 0) {
        g_row[ib + rl] = make_float2(expf(s1), expf(0.2f * s1));
        g_col[ib + rl] = make_float2(expf(s2), expf(0.2f * s2));
    }

    uint32_t hp[8];
#pragma unroll
    for (int p = 0; p < 8; p++) hp[p] = packh2(h[p * 2], h[p * 2 + 1]);
    *(uint4*)&hh[rl][cs]     = make_uint4(hp[0], hp[1], hp[2], hp[3]);
    *(uint4*)&hh[rl][cs + 8] = make_uint4(hp[4], hp[5], hp[6], hp[7]);
    __syncthreads();

    const int col = t >> 2, rs = (t & 3) * 16;
    uint32_t o[8];
#pragma unroll
    for (int p = 0; p < 8; p++) {
        __half2 v = __halves2half2(hh[rs + p * 2][col], hh[rs + p * 2 + 1][col]);
        o[p] = *(uint32_t*)&v;
    }
    *(uint4*)&g_hextT[(size_t)col * NN + ib + rs]     = make_uint4(o[0], o[1], o[2], o[3]);
    *(uint4*)&g_hextT[(size_t)col * NN + ib + rs + 8] = make_uint4(o[4], o[5], o[6], o[7]);
}

// ==================== K3: BK=128, two-wave adj, half the barriers ================
__global__ __launch_bounds__(256, 2) void k3_main(const int* __restrict__ adj) {
    __shared__ __half  w_sm[2][BM][PAD];     // 69.6 KB  A tile (fp16 weights)
    __shared__ __half  hT_sm[2][FOUT][PAD];  // 34.8 KB  B tile
    __shared__ float2  col_sm[4][BK];        // 4 KB     col factor ring
    __shared__ float2  row_sm[BM];           // 1 KB     row factors

    const int t    = threadIdx.x;
    const int warp = t >> 5, lane = t & 31;
    const int ib   = blockIdx.x * BM;
    const int j0   = blockIdx.y * JPER;

    const int seg  = t & 15;
    const int rloc = t >> 4;   // 0..15

    const int g = lane >> 2, tq = lane & 3;
    const int mrow = warp * 16;

    const uint32_t w_base  = smem_u32(&w_sm[0][0][0]);
    const uint32_t hT_base = smem_u32(&hT_sm[0][0][0]);
    const int a_tile = lane >> 3, a_rin = lane & 7;
    const uint32_t a_lane_off =
        (uint32_t)((mrow + a_rin + (a_tile & 1) * 8) * (PAD * 2) + (a_tile >> 1) * 16);
    const uint32_t b_lane_off =
        (uint32_t)((((lane >> 4) & 1) * 8 + (lane & 7)) * (PAD * 2) +
                   ((lane >> 3) & 1) * 16);

    float accf[NF][4];
    uint32_t acch[NF][2];
#pragma unroll
    for (int nf = 0; nf < NF; nf++) {
#pragma unroll
        for (int q = 0; q < 4; q++) accf[nf][q] = 0.f;
        acch[nf][0] = 0u; acch[nf][1] = 0u;
    }
    float dden[8];
#pragma unroll
    for (int q = 0; q < 8; q++) dden[q] = 0.f;

    auto stage_hT = [&](int buf, int it) {
        const int jg = j0 + it * BK;
#pragma unroll
        for (int m = 0; m < 4; m++) {
            int lin = t + m * 256;
            int n = lin >> 4, s2 = lin & 15;
            *(uint4*)&hT_sm[buf][n][s2 * 8] =
                *(const uint4*)&g_hextT[(size_t)n * NN + jg + s2 * 8];
        }
    };
    auto stage_col = [&](int slot, int it) {
        if (t < 128) col_sm[slot][t] = g_col[j0 + it * BK + t];
    };
    // load 8 int4 = one 64-j half-wave of adj for iteration `it`
    auto ld_adj = [&](int it, int half, int4* R) {
        const int* p = adj + (size_t)(ib + rloc) * NN + j0 + it * BK + half * 64 + seg * 4;
#pragma unroll
        for (int q = 0; q < 8; q++)
            R[q] = *(const int4*)&p[(size_t)q * 16 * NN];
    };
    auto gen_w = [&](int buf, int slot, int half, const int4* R) {
        const float2 c0 = col_sm[slot][half * 64 + seg * 4 + 0];
        const float2 c1 = col_sm[slot][half * 64 + seg * 4 + 1];
        const float2 c2 = col_sm[slot][half * 64 + seg * 4 + 2];
        const float2 c3 = col_sm[slot][half * 64 + seg * 4 + 3];
#pragma unroll
        for (int q = 0; q < 8; q++) {
            const float2 rv = row_sm[rloc + 16 * q];
            float w0 = wgen(rv, c0, R[q].x);
            float w1 = wgen(rv, c1, R[q].y);
            float w2 = wgen(rv, c2, R[q].z);
            float w3 = wgen(rv, c3, R[q].w);
            dden[q] += (w0 + w1) + (w2 + w3);
            uint2 p = make_uint2(packh2(w0, w1), packh2(w2, w3));
            *(uint2*)&w_sm[buf][rloc + 16 * q][half * 64 + seg * 4] = p;
        }
    };
    // mma over one 64-j half (k16 = half*4 .. half*4+3)
    auto mma_half = [&](int buf, int half) {
        const uint32_t wb = w_base + (uint32_t)buf * (BM * PAD * 2) + a_lane_off;
        const uint32_t hb = hT_base + (uint32_t)buf * (FOUT * PAD * 2) + b_lane_off;
#pragma unroll
        for (int k16 = 0; k16 < 4; k16++) {
            const uint32_t ko = (uint32_t)((half * 4 + k16) * 32);
            uint32_t a[4];
            ldsm_x4(a[0], a[1], a[2], a[3], wb + ko);
            const uint32_t kaddr = hb + ko;
#pragma unroll
            for (int nfp = 0; nfp < 4; nfp++) {
                uint32_t b00, b01, b10, b11;
                ldsm_x4(b00, b01, b10, b11,
                        kaddr + (uint32_t)(nfp * 16 * (PAD * 2)));
                uint32_t bl[2] = {b00, b01};
                mma16816h(acch[nfp * 2], a, bl);
                uint32_t bh[2] = {b10, b11};
                mma16816h(acch[nfp * 2 + 1], a, bh);
            }
        }
    };

    // ---- prologue: build iter 0's w tile ----
    {
        for (int m = t; m < BM; m += 256) row_sm[m] = g_row[ib + m];
        stage_col(0, 0);
        stage_col(1, 1);
        stage_hT(0, 0);
        int4 R[8];
        ld_adj(0, 0, R);
        __syncthreads();
        gen_w(0, 0, 0, R);
        ld_adj(0, 1, R);
        gen_w(0, 0, 1, R);
    }

    // ---- main loop: 16 iterations, one barrier each ----
    for (int it = 0; it < CHUNKS; it++) {
        const int buf = it & 1;
        const bool more = (it + 1 < CHUNKS);
        int4 R[8];
        if (more) ld_adj(it + 1, 0, R);   // wave 1: issued pre-barrier

        __syncthreads();   // w[buf], hT[buf] ready; all mma of it-1 complete

        if (more) {
            stage_hT(buf ^ 1, it + 1);
            if (it + 2 < CHUNKS) stage_col((it + 2) & 3, it + 2);
        }

        if (warp & 1) {    // wgen-first warps
            if (more) { gen_w(buf ^ 1, (it + 1) & 3, 0, R); ld_adj(it + 1, 1, R); }
            mma_half(buf, 0);
            if (more) gen_w(buf ^ 1, (it + 1) & 3, 1, R);
            mma_half(buf, 1);
        } else {           // mma-first warps
            mma_half(buf, 0);
            if (more) { gen_w(buf ^ 1, (it + 1) & 3, 0, R); ld_adj(it + 1, 1, R); }
            mma_half(buf, 1);
            if (more) gen_w(buf ^ 1, (it + 1) & 3, 1, R);
        }

        // flush fp16 partials to fp32 every iteration (128-j window, as before)
#pragma unroll
        for (int nf = 0; nf < NF; nf++) {
            float2 lo = __half22float2(*(__half2*)&acch[nf][0]);
            float2 hi = __half22float2(*(__half2*)&acch[nf][1]);
            accf[nf][0] += lo.x; accf[nf][1] += lo.y;
            accf[nf][2] += hi.x; accf[nf][3] += hi.y;
            acch[nf][0] = 0u; acch[nf][1] = 0u;
        }
    }

    // ---- denominator: reduce 16 seg lanes (half-warp) per row ----
#pragma unroll
    for (int q = 0; q < 8; q++) {
        float v = dden[q];
        v += __shfl_xor_sync(0xffffffffu, v, 1);
        v += __shfl_xor_sync(0xffffffffu, v, 2);
        v += __shfl_xor_sync(0xffffffffu, v, 4);
        v += __shfl_xor_sync(0xffffffffu, v, 8);
        if (seg == 0)
            g_den[blockIdx.y * NN + ib + rloc + 16 * q] = v;
    }

    // ---- store numerator partials ----
    float* P = &g_partial[(size_t)blockIdx.y * (NN * FOUT)];
    const int ra = ib + mrow + g;
    const int rb = ra + 8;
#pragma unroll
    for (int nf = 0; nf < NF; nf++) {
        const int col = nf * 8 + tq * 2;
        *(float2*)&P[(size_t)ra * FOUT + col] = make_float2(accf[nf][0], accf[nf][1]);
        *(float2*)&P[(size_t)rb * FOUT + col] = make_float2(accf[nf][2], accf[nf][3]);
    }
}

// ==================== K4: reduce splits, softmax divide, ELU ====================
__global__ __launch_bounds__(256) void k4_finish(float* __restrict__ out) {
    const int gid = blockIdx.x * 256 + threadIdx.x;   // 524288 total
    const int i = gid >> 6, f = gid & 63;
    float num = 0.f, den = 0.f;
#pragma unroll
    for (int s = 0; s < SPLITS; s++) {
        num += g_partial[((size_t)s * NN + i) * FOUT + f];
        den += g_den[s * NN + i];
    }
    float v = num / den;
    out[gid] = (v > 0.f) ? v : expm1f(v);
}

// ==================== launcher ====================
extern "C" void kernel_launch(void* const* d_in, const int* in_sizes, int n_in,
                              void* d_out, int out_size) {
    const float* inp   = (const float*)d_in[0];   // [8192,512]
    const int*   adj   = (const int*)d_in[1];     // [8192,8192]
    const float* W     = (const float*)d_in[2];   // [512,64]
    const float* a_vec = (const float*)d_in[3];   // [128,1]
    float* out = (float*)d_out;

    k0_dummy<<<1, 32>>>();                        // profiler alignment -> k3
    k1_gemm<<<dim3(NN / 64, KQ), 256>>>(inp, W);
    k2_prep<<<NN / 64, 256>>>(a_vec);
    k3_main<<<dim3(NN / BM, SPLITS), 256>>>(adj);
    k4_finish<<<(NN * FOUT) / 256, 256>>>(out);
}

// round 15
// speedup vs baseline: 1.0505x; 1.0505x over previous
#include <cuda_runtime.h>
#include <cuda_fp16.h>
#include <cuda_bf16.h>
#include <cstdint>

// Problem constants
#define NN   8192
#define FIN  512
#define FOUT 64
#define NF   8                // 64 N cols / 8 per mma
#define SPLITS 4
#define JPER  (NN / SPLITS)   // 2048 j per split
#define BK    64
#define CHUNKS (JPER / BK)    // 32
#define BM   128              // rows per k3 block
#define PAD  72               // smem row stride in halves (144B, ldmatrix conflict-free)
#define PADH 72               // k2 transpose tile stride
#define KQ   4                // k1 K-split factor

// -------- scratch (static device globals; no allocations allowed) --------
__device__ float   g_hp[KQ * NN * FOUT];          // 8.4 MB per-K-quarter h partials
__device__ __half2 g_rowh[NN];                    // (exp(f1), exp(0.2 f1)) fp16
__device__ __half  g_colEC[NN];                   // exp(f2) fp16
__device__ __half  g_colED[NN];                   // exp(0.2 f2) fp16
__device__ __half  g_hextT[FOUT * NN];            // 1 MB  transposed h fp16
__device__ float   g_partial[SPLITS * NN * FOUT]; // 8.4 MB per-split numerators
__device__ float   g_den[SPLITS * NN];            // per-split denominators
__device__ int     g_dummy_sink;

// -------- packed f32x2 FMA (Blackwell) --------
#define FMA_F32X2(d, a, b, c) \
    asm("fma.rn.f32x2 %0, %1, %2, %3;" : "=l"(d) : "l"(a), "l"(b), "l"(c))

// fp16-accumulator mma
__device__ __forceinline__ void mma16816h(uint32_t* c, const uint32_t* a,
                                          const uint32_t* b) {
    asm volatile(
        "mma.sync.aligned.m16n8k16.row.col.f16.f16.f16.f16 "
        "{%0,%1}, {%2,%3,%4,%5}, {%6,%7}, {%0,%1};"
        : "+r"(c[0]), "+r"(c[1])
        : "r"(a[0]), "r"(a[1]), "r"(a[2]), "r"(a[3]), "r"(b[0]), "r"(b[1]));
}

__device__ __forceinline__ void ldsm_x4(uint32_t& r0, uint32_t& r1, uint32_t& r2,
                                        uint32_t& r3, uint32_t addr) {
    asm volatile("ldmatrix.sync.aligned.m8n8.x4.shared.b16 {%0,%1,%2,%3}, [%4];"
                 : "=r"(r0), "=r"(r1), "=r"(r2), "=r"(r3) : "r"(addr));
}

__device__ __forceinline__ uint32_t smem_u32(const void* p) {
    uint32_t a;
    asm("{ .reg .u64 t; cvta.to.shared.u64 t, %1; cvt.u32.u64 %0, t; }"
        : "=r"(a) : "l"(p));
    return a;
}

__device__ __forceinline__ uint32_t packh2(float lo, float hi) {
    __half2 h = __floats2half2_rn(lo, hi);
    return *(uint32_t*)&h;
}

// ==================== K0: dummy (keeps profiler aligned on k3) ===================
__global__ void k0_dummy() {
    if (threadIdx.x == 1024) g_dummy_sink = 1;
}

// ==================== K1: h = inp @ W  (fp32, f32x2, K split 4-ways) ============
__global__ __launch_bounds__(256) void k1_gemm(const float* __restrict__ inp,
                                               const float* __restrict__ W) {
    __shared__ float inp_s[64][68];
    __shared__ float w_sT[64][66];    // stride 66: conflict-free b-operand LDS.64
    const int t  = threadIdx.x;
    const int i0 = blockIdx.x * 64;
    const int k0 = blockIdx.y * (FIN / KQ);
    const int tx = t & 15;
    const int ty = t >> 4;

    unsigned long long acc2[4][4];
#pragma unroll
    for (int q = 0; q < 4; q++)
#pragma unroll
        for (int c = 0; c < 4; c++) acc2[q][c] = 0ULL;

    for (int kc = k0; kc < k0 + FIN / KQ; kc += 64) {
#pragma unroll
        for (int m = 0; m < 4; m++) {
            int lin = t + 256 * m;
            int row = lin >> 4, seg = lin & 15;
            float4 v  = *(const float4*)&inp[(i0 + row) * FIN + kc + seg * 4];
            *(float4*)&inp_s[row][seg * 4] = v;
            float4 wv = *(const float4*)&W[(kc + row) * FOUT + seg * 4];
            w_sT[seg * 4 + 0][row] = wv.x;
            w_sT[seg * 4 + 1][row] = wv.y;
            w_sT[seg * 4 + 2][row] = wv.z;
            w_sT[seg * 4 + 3][row] = wv.w;
        }
        __syncthreads();
#pragma unroll 4
        for (int kk = 0; kk < 64; kk += 2) {
            unsigned long long a2[4], b2[4];
#pragma unroll
            for (int q = 0; q < 4; q++)
                a2[q] = *(const unsigned long long*)&inp_s[ty * 4 + q][kk];
#pragma unroll
            for (int c = 0; c < 4; c++)
                b2[c] = *(const unsigned long long*)&w_sT[tx * 4 + c][kk];
#pragma unroll
            for (int q = 0; q < 4; q++)
#pragma unroll
                for (int c = 0; c < 4; c++)
                    FMA_F32X2(acc2[q][c], a2[q], b2[c], acc2[q][c]);
        }
        __syncthreads();
    }
    float* HP = &g_hp[(size_t)blockIdx.y * NN * FOUT];
#pragma unroll
    for (int q = 0; q < 4; q++)
#pragma unroll
        for (int c = 0; c < 4; c++) {
            float lo, hi;
            asm("mov.b64 {%0,%1}, %2;" : "=f"(lo), "=f"(hi) : "l"(acc2[q][c]));
            HP[(size_t)(i0 + ty * 4 + q) * FOUT + tx * 4 + c] = lo + hi;
        }
}

// ==================== K2: sum quarters, exp factors (fp16), hT transpose ========
__global__ __launch_bounds__(256) void k2_prep(const float* __restrict__ a_vec) {
    __shared__ __half hh[64][PADH];
    __shared__ float as1[64], as2[64];

    const int t  = threadIdx.x;
    const int ib = blockIdx.x * 64;
    const int rl = t >> 2;          // local row 0..63
    const int cs = (t & 3) * 16;    // col segment

    if (t < 64)  as1[t] = a_vec[t];
    else if (t < 128) as2[t - 64] = a_vec[t];
    __syncthreads();

    float h[16];
#pragma unroll
    for (int p = 0; p < 4; p++) {
        float4 v = *(const float4*)&g_hp[(size_t)(ib + rl) * FOUT + cs + p * 4];
#pragma unroll
        for (int q = 1; q < KQ; q++) {
            float4 u = *(const float4*)&g_hp[(size_t)q * NN * FOUT +
                                             (size_t)(ib + rl) * FOUT + cs + p * 4];
            v.x += u.x; v.y += u.y; v.z += u.z; v.w += u.w;
        }
        h[p * 4 + 0] = v.x; h[p * 4 + 1] = v.y; h[p * 4 + 2] = v.z; h[p * 4 + 3] = v.w;
    }

    float s1 = 0.f, s2 = 0.f;
#pragma unroll
    for (int c = 0; c < 16; c++) {
        s1 += h[c] * as1[cs + c];
        s2 += h[c] * as2[cs + c];
    }
    s1 += __shfl_xor_sync(0xffffffffu, s1, 1);
    s1 += __shfl_xor_sync(0xffffffffu, s1, 2);
    s2 += __shfl_xor_sync(0xffffffffu, s2, 1);
    s2 += __shfl_xor_sync(0xffffffffu, s2, 2);
    if ((t & 3) == 0) {
        g_rowh[ib + rl]  = __floats2half2_rn(expf(s1), expf(0.2f * s1));
        g_colEC[ib + rl] = __float2half_rn(expf(s2));
        g_colED[ib + rl] = __float2half_rn(expf(0.2f * s2));
    }

    uint32_t hp[8];
#pragma unroll
    for (int p = 0; p < 8; p++) hp[p] = packh2(h[p * 2], h[p * 2 + 1]);
    *(uint4*)&hh[rl][cs]     = make_uint4(hp[0], hp[1], hp[2], hp[3]);
    *(uint4*)&hh[rl][cs + 8] = make_uint4(hp[4], hp[5], hp[6], hp[7]);
    __syncthreads();

    const int col = t >> 2, rs = (t & 3) * 16;
    uint32_t o[8];
#pragma unroll
    for (int p = 0; p < 8; p++) {
        __half2 v = __halves2half2(hh[rs + p * 2][col], hh[rs + p * 2 + 1][col]);
        o[p] = *(uint32_t*)&v;
    }
    *(uint4*)&g_hextT[(size_t)col * NN + ib + rs]     = make_uint4(o[0], o[1], o[2], o[3]);
    *(uint4*)&g_hextT[(size_t)col * NN + ib + rs + 8] = make_uint4(o[4], o[5], o[6], o[7]);
}

// ==================== K3: half2 wgen + fp16-acc MMA (R13 structure) =============
__global__ __launch_bounds__(256, 2) void k3_main(const int* __restrict__ adj) {
    __shared__ __half  w_sm[2][BM][PAD];     // 36.9 KB  A tile (fp16 weights)
    __shared__ __half  hT_sm[2][FOUT][PAD];  // 18.4 KB  B tile
    __shared__ __half2 colEC_sm[4][BK / 2];  // col factor rings (half2 j-pairs)
    __shared__ __half2 colED_sm[4][BK / 2];
    __shared__ __half2 row_smh[BM];          // row factors (EA, EB)

    const int t    = threadIdx.x;
    const int warp = t >> 5, lane = t & 31;
    const int ib   = blockIdx.x * BM;
    const int j0   = blockIdx.y * JPER;

    const int seg  = t & 15;
    const int rloc = t >> 4;   // 0..15
    const int jc0  = j0 + seg * 4;

    const int g = lane >> 2, tq = lane & 3;
    const int mrow = warp * 16;

    const uint32_t w_base  = smem_u32(&w_sm[0][0][0]);
    const uint32_t hT_base = smem_u32(&hT_sm[0][0][0]);
    const int a_tile = lane >> 3, a_rin = lane & 7;
    const uint32_t a_lane_off =
        (uint32_t)((mrow + a_rin + (a_tile & 1) * 8) * (PAD * 2) + (a_tile >> 1) * 16);
    const uint32_t b_lane_off =
        (uint32_t)((((lane >> 4) & 1) * 8 + (lane & 7)) * (PAD * 2) +
                   ((lane >> 3) & 1) * 16);

    float accf[NF][4];
    uint32_t acch[NF][2];
#pragma unroll
    for (int nf = 0; nf < NF; nf++) {
#pragma unroll
        for (int q = 0; q < 4; q++) accf[nf][q] = 0.f;
        acch[nf][0] = 0u; acch[nf][1] = 0u;
    }
    float dden[8];
    __half2 ddh[8];
#pragma unroll
    for (int q = 0; q < 8; q++) { dden[q] = 0.f; ddh[q] = __half2half2(__ushort_as_half(0)); }

    auto stage_hT = [&](int buf, int ch) {
        const int jg = j0 + ch * BK;
#pragma unroll
        for (int m = 0; m < 2; m++) {
            int lin = t + m * 256;
            int n = lin >> 3, s2 = lin & 7;
            *(uint4*)&hT_sm[buf][n][s2 * 8] =
                *(const uint4*)&g_hextT[(size_t)n * NN + jg + s2 * 8];
        }
    };
    auto stage_col = [&](int slot, int ch) {
        const int jp = (j0 + ch * BK) >> 1;    // half2 pair index
        if (t < 32)       colEC_sm[slot][t]      = ((const __half2*)g_colEC)[jp + t];
        else if (t < 64)  colED_sm[slot][t - 32] = ((const __half2*)g_colED)[jp + t - 32];
    };
    auto ld_adj = [&](int ch, int4* R) {
        const int* p = adj + (size_t)(ib + rloc) * NN + jc0 + ch * BK;
#pragma unroll
        for (int q = 0; q < 8; q++)
            R[q] = *(const int4*)&p[(size_t)q * 16 * NN];
    };
    auto gen_w = [&](int buf, int slot, const int4* R) {
        const __half2 EC01 = colEC_sm[slot][seg * 2];
        const __half2 EC23 = colEC_sm[slot][seg * 2 + 1];
        const __half2 ED01 = colED_sm[slot][seg * 2];
        const __half2 ED23 = colED_sm[slot][seg * 2 + 1];
#pragma unroll
        for (int q = 0; q < 8; q++) {
            const __half2 rv = row_smh[rloc + 16 * q];
            const __half2 h2a = __half2half2(__low2half(rv));
            const __half2 h2b = __half2half2(__high2half(rv));
            // masks: adj in {0,1}; 0x3C00 = fp16 1.0
            uint32_t mk01 = (uint32_t)R[q].x * 0x3C00u + (uint32_t)R[q].y * 0x3C000000u;
            uint32_t mk23 = (uint32_t)R[q].z * 0x3C00u + (uint32_t)R[q].w * 0x3C000000u;
            __half2 w01 = __hmax2(__hmul2(h2a, EC01), __hmul2(h2b, ED01));
            __half2 w23 = __hmax2(__hmul2(h2a, EC23), __hmul2(h2b, ED23));
            w01 = __hmul2(w01, *(__half2*)&mk01);
            w23 = __hmul2(w23, *(__half2*)&mk23);
            ddh[q] = __hadd2(ddh[q], __hadd2(w01, w23));
            uint2 p = make_uint2(*(uint32_t*)&w01, *(uint32_t*)&w23);
            *(uint2*)&w_sm[buf][rloc + 16 * q][seg * 4] = p;
        }
    };
    auto mma_chunk = [&](int buf) {
        const uint32_t wb = w_base + (uint32_t)buf * (BM * PAD * 2) + a_lane_off;
        const uint32_t hb = hT_base + (uint32_t)buf * (FOUT * PAD * 2) + b_lane_off;
#pragma unroll
        for (int k16 = 0; k16 < 4; k16++) {
            uint32_t a[4];
            ldsm_x4(a[0], a[1], a[2], a[3], wb + (uint32_t)(k16 * 32));
            const uint32_t kaddr = hb + (uint32_t)(k16 * 32);
#pragma unroll
            for (int nfp = 0; nfp < 4; nfp++) {
                uint32_t b00, b01, b10, b11;
                ldsm_x4(b00, b01, b10, b11,
                        kaddr + (uint32_t)(nfp * 16 * (PAD * 2)));
                uint32_t bl[2] = {b00, b01};
                mma16816h(acch[nfp * 2], a, bl);
                uint32_t bh[2] = {b10, b11};
                mma16816h(acch[nfp * 2 + 1], a, bh);
            }
        }
    };

    // ---- prologue ----
    {
        for (int m = t; m < BM; m += 256) row_smh[m] = g_rowh[ib + m];
        stage_col(0, 0);
        stage_col(1, 1);
        stage_hT(0, 0);
        int4 R[8];
        ld_adj(0, R);
        __syncthreads();
        gen_w(0, 0, R);
    }

    // ---- main loop ----
    for (int ch = 0; ch < CHUNKS; ch++) {
        const int buf = ch & 1;
        int4 R[8];
        if (ch + 1 < CHUNKS) ld_adj(ch + 1, R);

        __syncthreads();   // w[buf], hT[buf] ready; mma of ch-1 complete

        if (ch + 1 < CHUNKS) {
            stage_hT(buf ^ 1, ch + 1);
            if (ch + 2 < CHUNKS) stage_col((ch + 2) & 3, ch + 2);
        }

        if (warp & 1) {
            if (ch + 1 < CHUNKS) gen_w(buf ^ 1, (ch + 1) & 3, R);
            mma_chunk(buf);
        } else {
            mma_chunk(buf);
            if (ch + 1 < CHUNKS) gen_w(buf ^ 1, (ch + 1) & 3, R);
        }

        if (ch & 1) {   // flush fp16 partials to fp32 every 2 chunks
#pragma unroll
            for (int nf = 0; nf < NF; nf++) {
                float2 lo = __half22float2(*(__half2*)&acch[nf][0]);
                float2 hi = __half22float2(*(__half2*)&acch[nf][1]);
                accf[nf][0] += lo.x; accf[nf][1] += lo.y;
                accf[nf][2] += hi.x; accf[nf][3] += hi.y;
                acch[nf][0] = 0u; acch[nf][1] = 0u;
            }
#pragma unroll
            for (int q = 0; q < 8; q++) {
                float2 d = __half22float2(ddh[q]);
                dden[q] += d.x + d.y;
                ddh[q] = __half2half2(__ushort_as_half(0));
            }
        }
    }

    // ---- denominator: reduce 16 seg lanes (half-warp) per row ----
#pragma unroll
    for (int q = 0; q < 8; q++) {
        float v = dden[q];
        v += __shfl_xor_sync(0xffffffffu, v, 1);
        v += __shfl_xor_sync(0xffffffffu, v, 2);
        v += __shfl_xor_sync(0xffffffffu, v, 4);
        v += __shfl_xor_sync(0xffffffffu, v, 8);
        if (seg == 0)
            g_den[blockIdx.y * NN + ib + rloc + 16 * q] = v;
    }

    // ---- store numerator partials ----
    float* P = &g_partial[(size_t)blockIdx.y * (NN * FOUT)];
    const int ra = ib + mrow + g;
    const int rb = ra + 8;
#pragma unroll
    for (int nf = 0; nf < NF; nf++) {
        const int col = nf * 8 + tq * 2;
        *(float2*)&P[(size_t)ra * FOUT + col] = make_float2(accf[nf][0], accf[nf][1]);
        *(float2*)&P[(size_t)rb * FOUT + col] = make_float2(accf[nf][2], accf[nf][3]);
    }
}

// ==================== K4: reduce splits, softmax divide, ELU ====================
__global__ __launch_bounds__(256) void k4_finish(float* __restrict__ out) {
    const int gid = blockIdx.x * 256 + threadIdx.x;   // 524288 total
    const int i = gid >> 6, f = gid & 63;
    float num = 0.f, den = 0.f;
#pragma unroll
    for (int s = 0; s < SPLITS; s++) {
        num += g_partial[((size_t)s * NN + i) * FOUT + f];
        den += g_den[s * NN + i];
    }
    float v = num / den;
    out[gid] = (v > 0.f) ? v : expm1f(v);
}

// ==================== launcher ====================
extern "C" void kernel_launch(void* const* d_in, const int* in_sizes, int n_in,
                              void* d_out, int out_size) {
    const float* inp   = (const float*)d_in[0];   // [8192,512]
    const int*   adj   = (const int*)d_in[1];     // [8192,8192]
    const float* W     = (const float*)d_in[2];   // [512,64]
    const float* a_vec = (const float*)d_in[3];   // [128,1]
    float* out = (float*)d_out;

    k0_dummy<<<1, 32>>>();                        // profiler alignment -> k3
    k1_gemm<<<dim3(NN / 64, KQ), 256>>>(inp, W);
    k2_prep<<<NN / 64, 256>>>(a_vec);
    k3_main<<<dim3(NN / BM, SPLITS), 256>>>(adj);
    k4_finish<<<(NN * FOUT) / 256, 256>>>(out);
}

// round 16
// speedup vs baseline: 1.1089x; 1.0556x over previous
#include <cuda_runtime.h>
#include <cuda_fp16.h>
#include <cuda_bf16.h>
#include <cstdint>

// Problem constants
#define NN   8192
#define FIN  512
#define FOUT 64
#define NF   8                // 64 N cols / 8 per mma
#define SPLITS 4
#define JPER  (NN / SPLITS)   // 2048 j per split
#define BK    64
#define CHUNKS (JPER / BK)    // 32
#define BM   128              // rows per k3 block
#define PAD  72               // smem row stride in halves (144B, ldmatrix conflict-free)
#define PADH 72               // k2 transpose tile stride
#define KQ   8                // k1 K-split factor (64 k per block)

// -------- scratch (static device globals; no allocations allowed) --------
__device__ float   g_hp[KQ * NN * FOUT];          // 16.8 MB per-K-chunk h partials
__device__ __half2 g_rowh[NN];                    // (exp(f1), exp(0.2 f1)) fp16
__device__ __half  g_colEC[NN];                   // exp(f2) fp16
__device__ __half  g_colED[NN];                   // exp(0.2 f2) fp16
__device__ __half  g_hextT[FOUT * NN];            // 1 MB  transposed h fp16
__device__ float   g_partial[SPLITS * NN * FOUT]; // 8.4 MB per-split numerators
__device__ float   g_den[SPLITS * NN];            // per-split denominators
__device__ int     g_dummy_sink;

// -------- packed f32x2 FMA (Blackwell) --------
#define FMA_F32X2(d, a, b, c) \
    asm("fma.rn.f32x2 %0, %1, %2, %3;" : "=l"(d) : "l"(a), "l"(b), "l"(c))

// fp16-accumulator mma
__device__ __forceinline__ void mma16816h(uint32_t* c, const uint32_t* a,
                                          const uint32_t* b) {
    asm volatile(
        "mma.sync.aligned.m16n8k16.row.col.f16.f16.f16.f16 "
        "{%0,%1}, {%2,%3,%4,%5}, {%6,%7}, {%0,%1};"
        : "+r"(c[0]), "+r"(c[1])
        : "r"(a[0]), "r"(a[1]), "r"(a[2]), "r"(a[3]), "r"(b[0]), "r"(b[1]));
}

__device__ __forceinline__ void ldsm_x4(uint32_t& r0, uint32_t& r1, uint32_t& r2,
                                        uint32_t& r3, uint32_t addr) {
    asm volatile("ldmatrix.sync.aligned.m8n8.x4.shared.b16 {%0,%1,%2,%3}, [%4];"
                 : "=r"(r0), "=r"(r1), "=r"(r2), "=r"(r3) : "r"(addr));
}

__device__ __forceinline__ uint32_t smem_u32(const void* p) {
    uint32_t a;
    asm("{ .reg .u64 t; cvta.to.shared.u64 t, %1; cvt.u32.u64 %0, t; }"
        : "=r"(a) : "l"(p));
    return a;
}

__device__ __forceinline__ uint32_t packh2(float lo, float hi) {
    __half2 h = __floats2half2_rn(lo, hi);
    return *(uint32_t*)&h;
}

// ==================== K0: dummy (keeps profiler aligned on k3) ===================
__global__ void k0_dummy() {
    if (threadIdx.x == 1024) g_dummy_sink = 1;
}

// ==================== K1: h = inp @ W  (fp32, f32x2, K split 8-ways) ============
// grid (128 row-tiles, 8 K-chunks) = 1024 blocks -> ~4 resident/SM.
__global__ __launch_bounds__(256) void k1_gemm(const float* __restrict__ inp,
                                               const float* __restrict__ W) {
    __shared__ float inp_s[64][68];
    __shared__ float w_sT[64][66];    // stride 66: conflict-free b-operand LDS.64
    const int t  = threadIdx.x;
    const int i0 = blockIdx.x * 64;
    const int kc = blockIdx.y * (FIN / KQ);   // this block's 64-k chunk
    const int tx = t & 15;
    const int ty = t >> 4;

    unsigned long long acc2[4][4];
#pragma unroll
    for (int q = 0; q < 4; q++)
#pragma unroll
        for (int c = 0; c < 4; c++) acc2[q][c] = 0ULL;

    {
#pragma unroll
        for (int m = 0; m < 4; m++) {
            int lin = t + 256 * m;
            int row = lin >> 4, seg = lin & 15;
            float4 v  = *(const float4*)&inp[(i0 + row) * FIN + kc + seg * 4];
            *(float4*)&inp_s[row][seg * 4] = v;
            float4 wv = *(const float4*)&W[(kc + row) * FOUT + seg * 4];
            w_sT[seg * 4 + 0][row] = wv.x;
            w_sT[seg * 4 + 1][row] = wv.y;
            w_sT[seg * 4 + 2][row] = wv.z;
            w_sT[seg * 4 + 3][row] = wv.w;
        }
        __syncthreads();
#pragma unroll 4
        for (int kk = 0; kk < 64; kk += 2) {
            unsigned long long a2[4], b2[4];
#pragma unroll
            for (int q = 0; q < 4; q++)
                a2[q] = *(const unsigned long long*)&inp_s[ty * 4 + q][kk];
#pragma unroll
            for (int c = 0; c < 4; c++)
                b2[c] = *(const unsigned long long*)&w_sT[tx * 4 + c][kk];
#pragma unroll
            for (int q = 0; q < 4; q++)
#pragma unroll
                for (int c = 0; c < 4; c++)
                    FMA_F32X2(acc2[q][c], a2[q], b2[c], acc2[q][c]);
        }
    }
    float* HP = &g_hp[(size_t)blockIdx.y * NN * FOUT];
#pragma unroll
    for (int q = 0; q < 4; q++)
#pragma unroll
        for (int c = 0; c < 4; c++) {
            float lo, hi;
            asm("mov.b64 {%0,%1}, %2;" : "=f"(lo), "=f"(hi) : "l"(acc2[q][c]));
            HP[(size_t)(i0 + ty * 4 + q) * FOUT + tx * 4 + c] = lo + hi;
        }
}

// ==================== K2: sum chunks, exp factors (fp16), hT transpose ==========
__global__ __launch_bounds__(256) void k2_prep(const float* __restrict__ a_vec) {
    __shared__ __half hh[64][PADH];
    __shared__ float as1[64], as2[64];

    const int t  = threadIdx.x;
    const int ib = blockIdx.x * 64;
    const int rl = t >> 2;          // local row 0..63
    const int cs = (t & 3) * 16;    // col segment

    if (t < 64)  as1[t] = a_vec[t];
    else if (t < 128) as2[t - 64] = a_vec[t];
    __syncthreads();

    float h[16];
#pragma unroll
    for (int p = 0; p < 4; p++) {
        float4 v = *(const float4*)&g_hp[(size_t)(ib + rl) * FOUT + cs + p * 4];
#pragma unroll
        for (int q = 1; q < KQ; q++) {
            float4 u = *(const float4*)&g_hp[(size_t)q * NN * FOUT +
                                             (size_t)(ib + rl) * FOUT + cs + p * 4];
            v.x += u.x; v.y += u.y; v.z += u.z; v.w += u.w;
        }
        h[p * 4 + 0] = v.x; h[p * 4 + 1] = v.y; h[p * 4 + 2] = v.z; h[p * 4 + 3] = v.w;
    }

    float s1 = 0.f, s2 = 0.f;
#pragma unroll
    for (int c = 0; c < 16; c++) {
        s1 += h[c] * as1[cs + c];
        s2 += h[c] * as2[cs + c];
    }
    s1 += __shfl_xor_sync(0xffffffffu, s1, 1);
    s1 += __shfl_xor_sync(0xffffffffu, s1, 2);
    s2 += __shfl_xor_sync(0xffffffffu, s2, 1);
    s2 += __shfl_xor_sync(0xffffffffu, s2, 2);
    if ((t & 3) == 0) {
        g_rowh[ib + rl]  = __floats2half2_rn(expf(s1), expf(0.2f * s1));
        g_colEC[ib + rl] = __float2half_rn(expf(s2));
        g_colED[ib + rl] = __float2half_rn(expf(0.2f * s2));
    }

    uint32_t hp[8];
#pragma unroll
    for (int p = 0; p < 8; p++) hp[p] = packh2(h[p * 2], h[p * 2 + 1]);
    *(uint4*)&hh[rl][cs]     = make_uint4(hp[0], hp[1], hp[2], hp[3]);
    *(uint4*)&hh[rl][cs + 8] = make_uint4(hp[4], hp[5], hp[6], hp[7]);
    __syncthreads();

    const int col = t >> 2, rs = (t & 3) * 16;
    uint32_t o[8];
#pragma unroll
    for (int p = 0; p < 8; p++) {
        __half2 v = __halves2half2(hh[rs + p * 2][col], hh[rs + p * 2 + 1][col]);
        o[p] = *(uint32_t*)&v;
    }
    *(uint4*)&g_hextT[(size_t)col * NN + ib + rs]     = make_uint4(o[0], o[1], o[2], o[3]);
    *(uint4*)&g_hextT[(size_t)col * NN + ib + rs + 8] = make_uint4(o[4], o[5], o[6], o[7]);
}

// ==================== K3: half2 wgen + fp16-acc MMA (R15 config, banked) ========
__global__ __launch_bounds__(256, 2) void k3_main(const int* __restrict__ adj) {
    __shared__ __half  w_sm[2][BM][PAD];     // 36.9 KB  A tile (fp16 weights)
    __shared__ __half  hT_sm[2][FOUT][PAD];  // 18.4 KB  B tile
    __shared__ __half2 colEC_sm[4][BK / 2];  // col factor rings (half2 j-pairs)
    __shared__ __half2 colED_sm[4][BK / 2];
    __shared__ __half2 row_smh[BM];          // row factors (EA, EB)

    const int t    = threadIdx.x;
    const int warp = t >> 5, lane = t & 31;
    const int ib   = blockIdx.x * BM;
    const int j0   = blockIdx.y * JPER;

    const int seg  = t & 15;
    const int rloc = t >> 4;   // 0..15
    const int jc0  = j0 + seg * 4;

    const int g = lane >> 2, tq = lane & 3;
    const int mrow = warp * 16;

    const uint32_t w_base  = smem_u32(&w_sm[0][0][0]);
    const uint32_t hT_base = smem_u32(&hT_sm[0][0][0]);
    const int a_tile = lane >> 3, a_rin = lane & 7;
    const uint32_t a_lane_off =
        (uint32_t)((mrow + a_rin + (a_tile & 1) * 8) * (PAD * 2) + (a_tile >> 1) * 16);
    const uint32_t b_lane_off =
        (uint32_t)((((lane >> 4) & 1) * 8 + (lane & 7)) * (PAD * 2) +
                   ((lane >> 3) & 1) * 16);

    float accf[NF][4];
    uint32_t acch[NF][2];
#pragma unroll
    for (int nf = 0; nf < NF; nf++) {
#pragma unroll
        for (int q = 0; q < 4; q++) accf[nf][q] = 0.f;
        acch[nf][0] = 0u; acch[nf][1] = 0u;
    }
    float dden[8];
    __half2 ddh[8];
#pragma unroll
    for (int q = 0; q < 8; q++) { dden[q] = 0.f; ddh[q] = __half2half2(__ushort_as_half(0)); }

    auto stage_hT = [&](int buf, int ch) {
        const int jg = j0 + ch * BK;
#pragma unroll
        for (int m = 0; m < 2; m++) {
            int lin = t + m * 256;
            int n = lin >> 3, s2 = lin & 7;
            *(uint4*)&hT_sm[buf][n][s2 * 8] =
                *(const uint4*)&g_hextT[(size_t)n * NN + jg + s2 * 8];
        }
    };
    auto stage_col = [&](int slot, int ch) {
        const int jp = (j0 + ch * BK) >> 1;    // half2 pair index
        if (t < 32)       colEC_sm[slot][t]      = ((const __half2*)g_colEC)[jp + t];
        else if (t < 64)  colED_sm[slot][t - 32] = ((const __half2*)g_colED)[jp + t - 32];
    };
    auto ld_adj = [&](int ch, int4* R) {
        const int* p = adj + (size_t)(ib + rloc) * NN + jc0 + ch * BK;
#pragma unroll
        for (int q = 0; q < 8; q++)
            R[q] = *(const int4*)&p[(size_t)q * 16 * NN];
    };
    auto gen_w = [&](int buf, int slot, const int4* R) {
        const __half2 EC01 = colEC_sm[slot][seg * 2];
        const __half2 EC23 = colEC_sm[slot][seg * 2 + 1];
        const __half2 ED01 = colED_sm[slot][seg * 2];
        const __half2 ED23 = colED_sm[slot][seg * 2 + 1];
#pragma unroll
        for (int q = 0; q < 8; q++) {
            const __half2 rv = row_smh[rloc + 16 * q];
            const __half2 h2a = __half2half2(__low2half(rv));
            const __half2 h2b = __half2half2(__high2half(rv));
            uint32_t mk01 = (uint32_t)R[q].x * 0x3C00u + (uint32_t)R[q].y * 0x3C000000u;
            uint32_t mk23 = (uint32_t)R[q].z * 0x3C00u + (uint32_t)R[q].w * 0x3C000000u;
            __half2 w01 = __hmax2(__hmul2(h2a, EC01), __hmul2(h2b, ED01));
            __half2 w23 = __hmax2(__hmul2(h2a, EC23), __hmul2(h2b, ED23));
            w01 = __hmul2(w01, *(__half2*)&mk01);
            w23 = __hmul2(w23, *(__half2*)&mk23);
            ddh[q] = __hadd2(ddh[q], __hadd2(w01, w23));
            uint2 p = make_uint2(*(uint32_t*)&w01, *(uint32_t*)&w23);
            *(uint2*)&w_sm[buf][rloc + 16 * q][seg * 4] = p;
        }
    };
    auto mma_chunk = [&](int buf) {
        const uint32_t wb = w_base + (uint32_t)buf * (BM * PAD * 2) + a_lane_off;
        const uint32_t hb = hT_base + (uint32_t)buf * (FOUT * PAD * 2) + b_lane_off;
#pragma unroll
        for (int k16 = 0; k16 < 4; k16++) {
            uint32_t a[4];
            ldsm_x4(a[0], a[1], a[2], a[3], wb + (uint32_t)(k16 * 32));
            const uint32_t kaddr = hb + (uint32_t)(k16 * 32);
#pragma unroll
            for (int nfp = 0; nfp < 4; nfp++) {
                uint32_t b00, b01, b10, b11;
                ldsm_x4(b00, b01, b10, b11,
                        kaddr + (uint32_t)(nfp * 16 * (PAD * 2)));
                uint32_t bl[2] = {b00, b01};
                mma16816h(acch[nfp * 2], a, bl);
                uint32_t bh[2] = {b10, b11};
                mma16816h(acch[nfp * 2 + 1], a, bh);
            }
        }
    };

    // ---- prologue ----
    {
        for (int m = t; m < BM; m += 256) row_smh[m] = g_rowh[ib + m];
        stage_col(0, 0);
        stage_col(1, 1);
        stage_hT(0, 0);
        int4 R[8];
        ld_adj(0, R);
        __syncthreads();
        gen_w(0, 0, R);
    }

    // ---- main loop ----
    for (int ch = 0; ch < CHUNKS; ch++) {
        const int buf = ch & 1;
        int4 R[8];
        if (ch + 1 < CHUNKS) ld_adj(ch + 1, R);

        __syncthreads();   // w[buf], hT[buf] ready; mma of ch-1 complete

        if (ch + 1 < CHUNKS) {
            stage_hT(buf ^ 1, ch + 1);
            if (ch + 2 < CHUNKS) stage_col((ch + 2) & 3, ch + 2);
        }

        if (warp & 1) {
            if (ch + 1 < CHUNKS) gen_w(buf ^ 1, (ch + 1) & 3, R);
            mma_chunk(buf);
        } else {
            mma_chunk(buf);
            if (ch + 1 < CHUNKS) gen_w(buf ^ 1, (ch + 1) & 3, R);
        }

        if (ch & 1) {   // flush fp16 partials to fp32 every 2 chunks
#pragma unroll
            for (int nf = 0; nf < NF; nf++) {
                float2 lo = __half22float2(*(__half2*)&acch[nf][0]);
                float2 hi = __half22float2(*(__half2*)&acch[nf][1]);
                accf[nf][0] += lo.x; accf[nf][1] += lo.y;
                accf[nf][2] += hi.x; accf[nf][3] += hi.y;
                acch[nf][0] = 0u; acch[nf][1] = 0u;
            }
#pragma unroll
            for (int q = 0; q < 8; q++) {
                float2 d = __half22float2(ddh[q]);
                dden[q] += d.x + d.y;
                ddh[q] = __half2half2(__ushort_as_half(0));
            }
        }
    }

    // ---- denominator: reduce 16 seg lanes (half-warp) per row ----
#pragma unroll
    for (int q = 0; q < 8; q++) {
        float v = dden[q];
        v += __shfl_xor_sync(0xffffffffu, v, 1);
        v += __shfl_xor_sync(0xffffffffu, v, 2);
        v += __shfl_xor_sync(0xffffffffu, v, 4);
        v += __shfl_xor_sync(0xffffffffu, v, 8);
        if (seg == 0)
            g_den[blockIdx.y * NN + ib + rloc + 16 * q] = v;
    }

    // ---- store numerator partials ----
    float* P = &g_partial[(size_t)blockIdx.y * (NN * FOUT)];
    const int ra = ib + mrow + g;
    const int rb = ra + 8;
#pragma unroll
    for (int nf = 0; nf < NF; nf++) {
        const int col = nf * 8 + tq * 2;
        *(float2*)&P[(size_t)ra * FOUT + col] = make_float2(accf[nf][0], accf[nf][1]);
        *(float2*)&P[(size_t)rb * FOUT + col] = make_float2(accf[nf][2], accf[nf][3]);
    }
}

// ==================== K4: reduce splits, softmax divide, ELU (float4) ===========
__global__ __launch_bounds__(256) void k4_finish(float* __restrict__ out) {
    const int gid = blockIdx.x * 256 + threadIdx.x;   // 131072 total (x4 outputs)
    const int i = gid >> 4, f4 = (gid & 15) * 4;
    float4 num = make_float4(0.f, 0.f, 0.f, 0.f);
    float den = 0.f;
#pragma unroll
    for (int s = 0; s < SPLITS; s++) {
        float4 u = *(const float4*)&g_partial[((size_t)s * NN + i) * FOUT + f4];
        num.x += u.x; num.y += u.y; num.z += u.z; num.w += u.w;
        den += g_den[s * NN + i];
    }
    float r = 1.f / den;
    float v0 = num.x * r, v1 = num.y * r, v2 = num.z * r, v3 = num.w * r;
    float4 o;
    o.x = (v0 > 0.f) ? v0 : expm1f(v0);
    o.y = (v1 > 0.f) ? v1 : expm1f(v1);
    o.z = (v2 > 0.f) ? v2 : expm1f(v2);
    o.w = (v3 > 0.f) ? v3 : expm1f(v3);
    *(float4*)&out[(size_t)i * FOUT + f4] = o;
}

// ==================== launcher ====================
extern "C" void kernel_launch(void* const* d_in, const int* in_sizes, int n_in,
                              void* d_out, int out_size) {
    const float* inp   = (const float*)d_in[0];   // [8192,512]
    const int*   adj   = (const int*)d_in[1];     // [8192,8192]
    const float* W     = (const float*)d_in[2];   // [512,64]
    const float* a_vec = (const float*)d_in[3];   // [128,1]
    float* out = (float*)d_out;

    k0_dummy<<<1, 32>>>();                        // profiler alignment -> k3
    k1_gemm<<<dim3(NN / 64, KQ), 256>>>(inp, W);
    k2_prep<<<NN / 64, 256>>>(a_vec);
    k3_main<<<dim3(NN / BM, SPLITS), 256>>>(adj);
    k4_finish<<<(NN * FOUT / 4) / 256, 256>>>(out);
}